// round 17
// baseline (speedup 1.0000x reference)
#include <cuda_runtime.h>
#include <cuda_bf16.h>
#include <cstdint>

#define Bb 4096
#define Tt 128
#define Ff 64
#define Hh 32

typedef unsigned long long u64;

// xz in gate-pair-interleaved u64 form: xzp[row][p] with
//   p in [0,32):  (z_i[p],    z_f[p])      = (z[p],    z[32+p])
//   p in [32,64): (z_g[p-32], z_o[p-32])   = (z[64+q], z[96+q])
__device__ u64 g_xzp[(size_t)Bb * Tt * 64];

// B images for HMMA: Bt[n][k] = We[k][n], bf16 hi/lo, plain [128][64]
__device__ __align__(16) unsigned short g_Bth[128 * 64];
__device__ __align__(16) unsigned short g_Btl[128 * 64];
// be packed into gate-pair u64s
__device__ u64 g_bep[64];

// ---------- f32x2 packed helpers ----------
__device__ __forceinline__ u64 pk2(float lo, float hi) {
    u64 r; asm("mov.b64 %0, {%1, %2};" : "=l"(r) : "f"(lo), "f"(hi)); return r;
}
__device__ __forceinline__ void upk2(u64 v, float &lo, float &hi) {
    asm("mov.b64 {%0, %1}, %2;" : "=f"(lo), "=f"(hi) : "l"(v));
}
__device__ __forceinline__ u64 fma2(u64 a, u64 b, u64 c) {
    u64 d; asm("fma.rn.f32x2 %0, %1, %2, %3;" : "=l"(d) : "l"(a), "l"(b), "l"(c)); return d;
}
__device__ __forceinline__ u64 add2(u64 a, u64 b) {
    u64 d; asm("add.rn.f32x2 %0, %1, %2;" : "=l"(d) : "l"(a), "l"(b)); return d;
}

// ---------- cp.async helpers ----------
__device__ __forceinline__ void cpa16(void* dst, const void* src) {
    unsigned ds = (unsigned)__cvta_generic_to_shared(dst);
    asm volatile("cp.async.ca.shared.global [%0], [%1], 16;" :: "r"(ds), "l"(src));
}
__device__ __forceinline__ void cpa_commit() {
    asm volatile("cp.async.commit_group;");
}
template<int N> __device__ __forceinline__ void cpa_wait() {
    asm volatile("cp.async.wait_group %0;" :: "n"(N));
}

__device__ __forceinline__ float sigf(float x) {
    return __fdividef(1.0f, 1.0f + __expf(-x));
}
__device__ __forceinline__ float cellf(float zi, float zf, float zg, float zo, float &c) {
    float i = sigf(zi);
    float f = sigf(zf);
    float g = fmaxf(zg, 0.0f);
    float o = sigf(zo);
    c = fmaf(f, c, i * g);
    return o * fmaxf(c, 0.0f);
}

__device__ __forceinline__ unsigned short bf16bits(float f) {
    __nv_bfloat16 b = __float2bfloat16(f);
    return *reinterpret_cast<unsigned short*>(&b);
}
__device__ __forceinline__ float bf16val(unsigned short s) {
    __nv_bfloat16 b = *reinterpret_cast<__nv_bfloat16*>(&s);
    return __bfloat162float(b);
}

// mma.sync m16n8k16 bf16 -> f32 (sm_80+ PTX, works on sm_103 base target)
__device__ __forceinline__ void mma16816(float* d,
                                         uint32_t a0, uint32_t a1, uint32_t a2, uint32_t a3,
                                         uint32_t b0, uint32_t b1) {
    asm volatile("mma.sync.aligned.m16n8k16.row.col.f32.bf16.bf16.f32 "
                 "{%0,%1,%2,%3}, {%4,%5,%6,%7}, {%8,%9}, {%0,%1,%2,%3};"
                 : "+f"(d[0]), "+f"(d[1]), "+f"(d[2]), "+f"(d[3])
                 : "r"(a0), "r"(a1), "r"(a2), "r"(a3), "r"(b0), "r"(b1));
}

// SMEM layout for k_xz (dynamic). bf16 rows padded to 72 elems (144B).
#define AS_HI 0
#define AS_LO 9216
#define BS_HI 18432
#define BS_LO 36864
#define SMX_TOTAL 55296

// =====================================================================
// Kernel 0: prep — bf16 hi/lo images of B (Bt[n][k] = We[k][n]) + be pairs.
// =====================================================================
__global__ void k_prep(const float* __restrict__ We, const float* __restrict__ be)
{
    const int tid = threadIdx.x;
    for (int e = tid; e < 128 * 64; e += 256) {
        int n = e >> 6, k = e & 63;
        float v = __ldg(We + k * 128 + n);
        unsigned short hi = bf16bits(v);
        unsigned short lo = bf16bits(v - bf16val(hi));
        g_Bth[n * 64 + k] = hi;
        g_Btl[n * 64 + k] = lo;
    }
    for (int p = tid; p < 64; p += 256) {
        int a = (p < 32) ? p : (64 + (p - 32));
        g_bep[p] = pk2(__ldg(be + a), __ldg(be + a + 32));
    }
}

// =====================================================================
// Kernel 1: xz = x @ We + be via mma.sync bf16-split (verbatim R11/R14)
// =====================================================================
__global__ __launch_bounds__(128) void k_xz(const float* __restrict__ x)
{
    extern __shared__ __align__(16) char sm[];
    const int tid = threadIdx.x;
    const int wid = tid >> 5;
    const int lane = tid & 31;
    const int g = lane >> 2, t = lane & 3;

    for (int i = tid; i < 1024; i += 128) {
        int row = i >> 3, grp = i & 7;
        *(uint4*)(sm + BS_HI + row * 144 + grp * 16) = __ldg((const uint4*)g_Bth + i);
        *(uint4*)(sm + BS_LO + row * 144 + grp * 16) = __ldg((const uint4*)g_Btl + i);
    }
    {
        const float4* xb = (const float4*)(x + (size_t)blockIdx.x * 64 * 64);
        for (int i = tid; i < 1024; i += 128) {
            int row = i >> 4, kq = i & 15;
            float4 v = __ldg(xb + i);
            float vs[4] = {v.x, v.y, v.z, v.w};
            unsigned short hi[4], lo[4];
#pragma unroll
            for (int j = 0; j < 4; j++) {
                hi[j] = bf16bits(vs[j]);
                lo[j] = bf16bits(vs[j] - bf16val(hi[j]));
            }
            *(uint2*)(sm + AS_HI + row * 144 + kq * 8) = *(uint2*)hi;
            *(uint2*)(sm + AS_LO + row * 144 + kq * 8) = *(uint2*)lo;
        }
    }
    __syncthreads();

    const int rowlo = wid * 16;
    const char* Ah = sm + AS_HI + (rowlo + g) * 144 + t * 4;
    const char* Al = sm + AS_LO + (rowlo + g) * 144 + t * 4;
    const char* Bh = sm + BS_HI + g * 144 + t * 4;
    const char* Bl = sm + BS_LO + g * 144 + t * 4;

    float acc[16][4];
#pragma unroll
    for (int j = 0; j < 16; j++)
#pragma unroll
        for (int q = 0; q < 4; q++) acc[j][q] = 0.0f;

#pragma unroll
    for (int ks = 0; ks < 4; ks++) {
        const int ko = ks * 32;
        uint32_t ah0 = *(const uint32_t*)(Ah + ko);
        uint32_t ah1 = *(const uint32_t*)(Ah + ko + 1152);
        uint32_t ah2 = *(const uint32_t*)(Ah + ko + 16);
        uint32_t ah3 = *(const uint32_t*)(Ah + ko + 1152 + 16);
        uint32_t al0 = *(const uint32_t*)(Al + ko);
        uint32_t al1 = *(const uint32_t*)(Al + ko + 1152);
        uint32_t al2 = *(const uint32_t*)(Al + ko + 16);
        uint32_t al3 = *(const uint32_t*)(Al + ko + 1152 + 16);
#pragma unroll
        for (int j = 0; j < 16; j++) {
            const char* bh = Bh + j * 1152 + ko;
            const char* bl = Bl + j * 1152 + ko;
            uint32_t bh0 = *(const uint32_t*)bh;
            uint32_t bh1 = *(const uint32_t*)(bh + 16);
            uint32_t bl0 = *(const uint32_t*)bl;
            uint32_t bl1 = *(const uint32_t*)(bl + 16);
            mma16816(acc[j], ah0, ah1, ah2, ah3, bh0, bh1);
            mma16816(acc[j], al0, al1, al2, al3, bh0, bh1);
            mma16816(acc[j], ah0, ah1, ah2, ah3, bl0, bl1);
        }
    }

    const size_t r0 = (size_t)blockIdx.x * 64 + rowlo + g;
    const size_t r1 = r0 + 8;
#pragma unroll
    for (int half = 0; half < 2; half++) {
#pragma unroll
        for (int jj = 0; jj < 4; jj++) {
            int j = half * 8 + jj;
            int p = half * 32 + jj * 8 + 2 * t;
            ulonglong2 bb = *(const ulonglong2*)&g_bep[p];
            ulonglong2 s0, s1;
            s0.x = add2(pk2(acc[j][0], acc[j + 4][0]), bb.x);
            s0.y = add2(pk2(acc[j][1], acc[j + 4][1]), bb.y);
            s1.x = add2(pk2(acc[j][2], acc[j + 4][2]), bb.x);
            s1.y = add2(pk2(acc[j][3], acc[j + 4][3]), bb.y);
            *(ulonglong2*)&g_xzp[r0 * 64 + p] = s0;
            *(ulonglong2*)&g_xzp[r1 * 64 + p] = s1;
        }
    }
}

// =====================================================================
// Kernel 2: fused encoder + decoder + Dense(64).
// CTA = 64 thr = 2 warps carrying TWO independent teams (4 batch rows).
// Warp w owns kk slice [16w,16w+16) (U regs SHARED across teams) and
// finalizes row w of each team. Teams are sequential blocks inside each
// step -> 2x independent work per warp hides the serial exchange/cell/
// barrier tail that capped issue at 51%. Barriers shared by both teams.
// Grid 1024.
// =====================================================================
__global__ __launch_bounds__(64) void k_rnn(const float* __restrict__ Ue,
                                            const float* __restrict__ Ud,
                                            const float* __restrict__ Wd,
                                            const float* __restrict__ bd,
                                            const float* __restrict__ Wout,
                                            const float* __restrict__ bout,
                                            float* __restrict__ y)
{
    __shared__ __align__(16) u64 Wos[32 * 32];        // 8KB
    __shared__ __align__(16) u64 ring[2][2][4][64];   // 8KB [team][w][slot][idx]
    __shared__ __align__(16) u64 hds[2][4][32];       // 2KB [buf][2c+w][kk]
    __shared__ __align__(16) u64 px[2][2][3][32];     // 6KB [team][srcw][v][lane]

    const int tid = threadIdx.x;
    const int lane = tid & 31;
    const int wid = tid >> 5;
    const int ow = wid ^ 1;
    const int R = blockIdx.x * 4;
    const int base = wid * 16;

    for (int i = tid; i < 32 * 32; i += 64) {
        int kk = i >> 5, l = i & 31;
        Wos[i] = pk2(__ldg(Wout + kk * 64 + l), __ldg(Wout + kk * 64 + 32 + l));
    }

    // ---------------- encoder ----------------
    u64 wif[16], wgo[16];
#pragma unroll
    for (int j = 0; j < 16; j++) {
        const float* u = Ue + (base + j) * 128;
        wif[j] = pk2(__ldg(u + lane),      __ldg(u + 32 + lane));
        wgo[j] = pk2(__ldg(u + 64 + lane), __ldg(u + 96 + lane));
    }

    const u64* xz0 = g_xzp + (size_t)(R + wid) * 128 * 64;       // team0 row
    const u64* xz1 = g_xzp + (size_t)(R + 2 + wid) * 128 * 64;   // team1 row
#pragma unroll
    for (int p = 0; p < 3; p++) {
        cpa16(&ring[0][wid][p][lane * 2], xz0 + (size_t)p * 64 + lane * 2);
        cpa16(&ring[1][wid][p][lane * 2], xz1 + (size_t)p * 64 + lane * 2);
        cpa_commit();
    }

    hds[0][wid][lane] = 0ULL; hds[0][2 + wid][lane] = 0ULL;
    hds[1][wid][lane] = 0ULL; hds[1][2 + wid][lane] = 0ULL;
    cpa_wait<2>();
    __syncthreads();

    float h0 = 0.f, cc0 = 0.f, h1 = 0.f, cc1 = 0.f;

    for (int t = 0; t < 128; t++) {
        const int cb = t & 1;
        if (t < 125) {
            cpa16(&ring[0][wid][(t + 3) & 3][lane * 2], xz0 + (size_t)(t + 3) * 64 + lane * 2);
            cpa16(&ring[1][wid][(t + 3) & 3][lane * 2], xz1 + (size_t)(t + 3) * 64 + lane * 2);
            cpa_commit();
        }

        // ---- team 0 fma block ----
        const u64* s0 = ring[0][wid][t & 3];
        u64 am0 = s0[lane], gm0 = s0[32 + lane];
        {
            u64 ao = 0ULL, go = 0ULL;
#pragma unroll
            for (int j = 0; j < 16; j += 2) {
                ulonglong2 hm2 = *(const ulonglong2*)&hds[cb][wid][base + j];
                ulonglong2 ho2 = *(const ulonglong2*)&hds[cb][ow][base + j];
                am0 = fma2(hm2.x, wif[j], am0);
                gm0 = fma2(hm2.x, wgo[j], gm0);
                ao  = fma2(ho2.x, wif[j], ao);
                go  = fma2(ho2.x, wgo[j], go);
                am0 = fma2(hm2.y, wif[j + 1], am0);
                gm0 = fma2(hm2.y, wgo[j + 1], gm0);
                ao  = fma2(ho2.y, wif[j + 1], ao);
                go  = fma2(ho2.y, wgo[j + 1], go);
            }
            px[0][wid][0][lane] = ao;
            px[0][wid][1][lane] = go;
        }

        // ---- team 1 fma block ----
        const u64* s1 = ring[1][wid][t & 3];
        u64 am1 = s1[lane], gm1 = s1[32 + lane];
        {
            u64 ao = 0ULL, go = 0ULL;
#pragma unroll
            for (int j = 0; j < 16; j += 2) {
                ulonglong2 hm2 = *(const ulonglong2*)&hds[cb][2 + wid][base + j];
                ulonglong2 ho2 = *(const ulonglong2*)&hds[cb][2 + ow][base + j];
                am1 = fma2(hm2.x, wif[j], am1);
                gm1 = fma2(hm2.x, wgo[j], gm1);
                ao  = fma2(ho2.x, wif[j], ao);
                go  = fma2(ho2.x, wgo[j], go);
                am1 = fma2(hm2.y, wif[j + 1], am1);
                gm1 = fma2(hm2.y, wgo[j + 1], gm1);
                ao  = fma2(ho2.y, wif[j + 1], ao);
                go  = fma2(ho2.y, wgo[j + 1], go);
            }
            px[1][wid][0][lane] = ao;
            px[1][wid][1][lane] = go;
        }

        __syncthreads();
        u64 aif0 = add2(am0, px[0][ow][0][lane]);
        u64 ago0 = add2(gm0, px[0][ow][1][lane]);
        u64 aif1 = add2(am1, px[1][ow][0][lane]);
        u64 ago1 = add2(gm1, px[1][ow][1][lane]);

        float zi, zf, zg, zo;
        upk2(aif0, zi, zf); upk2(ago0, zg, zo);
        h0 = cellf(zi, zf, zg, zo, cc0);
        upk2(aif1, zi, zf); upk2(ago1, zg, zo);
        h1 = cellf(zi, zf, zg, zo, cc1);

        const int nb = cb ^ 1;
        hds[nb][wid][lane] = pk2(h0, h0);
        hds[nb][2 + wid][lane] = pk2(h1, h1);
        if (t < 125) cpa_wait<2>(); else cpa_wait<0>();
        __syncthreads();
    }

    // ---------------- zd = hT @ Wd + bd (both teams, shared Wd loads) ----
    u64 zif0 = pk2(__ldg(bd + lane),      __ldg(bd + 32 + lane));
    u64 zgo0 = pk2(__ldg(bd + 64 + lane), __ldg(bd + 96 + lane));
    u64 zif1 = zif0, zgo1 = zgo0;
    {
        float ht0 = h0, ht1 = h1;
#pragma unroll
        for (int kk = 0; kk < 32; kk++) {
            float hv0 = __shfl_sync(0xffffffffu, ht0, kk);
            float hv1 = __shfl_sync(0xffffffffu, ht1, kk);
            const float* w = Wd + kk * 128;
            u64 vif = pk2(__ldg(w + lane),      __ldg(w + 32 + lane));
            u64 vgo = pk2(__ldg(w + 64 + lane), __ldg(w + 96 + lane));
            u64 hp0 = pk2(hv0, hv0);
            u64 hp1 = pk2(hv1, hv1);
            zif0 = fma2(hp0, vif, zif0);
            zgo0 = fma2(hp0, vgo, zgo0);
            zif1 = fma2(hp1, vif, zif1);
            zgo1 = fma2(hp1, vgo, zgo1);
        }
    }

    // ---------------- decoder (reload U = Ud slice) ----------------
#pragma unroll
    for (int j = 0; j < 16; j++) {
        const float* u = Ud + (base + j) * 128;
        wif[j] = pk2(__ldg(u + lane),      __ldg(u + 32 + lane));
        wgo[j] = pk2(__ldg(u + 64 + lane), __ldg(u + 96 + lane));
    }

    hds[0][wid][lane] = 0ULL; hds[0][2 + wid][lane] = 0ULL;
    hds[1][wid][lane] = 0ULL; hds[1][2 + wid][lane] = 0ULL;
    __syncthreads();

    h0 = 0.f; cc0 = 0.f; h1 = 0.f; cc1 = 0.f;
    u64 bo = pk2(__ldg(bout + lane), __ldg(bout + 32 + lane));
    float* yA = y + (size_t)(R + wid) * 128 * 64;
    float* yB = y + (size_t)(R + 2 + wid) * 128 * 64;

    for (int t = 0; t < 128; t++) {
        const int cb = t & 1;

        // ---- team 0 ----
        u64 am0 = zif0, gm0 = zgo0, ym0 = bo;
        {
            u64 ao = 0ULL, go = 0ULL, yo = 0ULL;
#pragma unroll
            for (int j = 0; j < 16; j += 2) {
                ulonglong2 hm2 = *(const ulonglong2*)&hds[cb][wid][base + j];
                ulonglong2 ho2 = *(const ulonglong2*)&hds[cb][ow][base + j];
                u64 wo0 = Wos[(base + j) * 32 + lane];
                u64 wo1 = Wos[(base + j + 1) * 32 + lane];
                am0 = fma2(hm2.x, wif[j], am0);
                gm0 = fma2(hm2.x, wgo[j], gm0);
                ym0 = fma2(hm2.x, wo0, ym0);
                ao  = fma2(ho2.x, wif[j], ao);
                go  = fma2(ho2.x, wgo[j], go);
                yo  = fma2(ho2.x, wo0, yo);
                am0 = fma2(hm2.y, wif[j + 1], am0);
                gm0 = fma2(hm2.y, wgo[j + 1], gm0);
                ym0 = fma2(hm2.y, wo1, ym0);
                ao  = fma2(ho2.y, wif[j + 1], ao);
                go  = fma2(ho2.y, wgo[j + 1], go);
                yo  = fma2(ho2.y, wo1, yo);
            }
            px[0][wid][0][lane] = ao;
            px[0][wid][1][lane] = go;
            px[0][wid][2][lane] = yo;
        }

        // ---- team 1 ----
        u64 am1 = zif1, gm1 = zgo1, ym1 = bo;
        {
            u64 ao = 0ULL, go = 0ULL, yo = 0ULL;
#pragma unroll
            for (int j = 0; j < 16; j += 2) {
                ulonglong2 hm2 = *(const ulonglong2*)&hds[cb][2 + wid][base + j];
                ulonglong2 ho2 = *(const ulonglong2*)&hds[cb][2 + ow][base + j];
                u64 wo0 = Wos[(base + j) * 32 + lane];
                u64 wo1 = Wos[(base + j + 1) * 32 + lane];
                am1 = fma2(hm2.x, wif[j], am1);
                gm1 = fma2(hm2.x, wgo[j], gm1);
                ym1 = fma2(hm2.x, wo0, ym1);
                ao  = fma2(ho2.x, wif[j], ao);
                go  = fma2(ho2.x, wgo[j], go);
                yo  = fma2(ho2.x, wo0, yo);
                am1 = fma2(hm2.y, wif[j + 1], am1);
                gm1 = fma2(hm2.y, wgo[j + 1], gm1);
                ym1 = fma2(hm2.y, wo1, ym1);
                ao  = fma2(ho2.y, wif[j + 1], ao);
                go  = fma2(ho2.y, wgo[j + 1], go);
                yo  = fma2(ho2.y, wo1, yo);
            }
            px[1][wid][0][lane] = ao;
            px[1][wid][1][lane] = go;
            px[1][wid][2][lane] = yo;
        }

        __syncthreads();
        u64 aif0 = add2(am0, px[0][ow][0][lane]);
        u64 ago0 = add2(gm0, px[0][ow][1][lane]);
        u64 ya0  = add2(ym0, px[0][ow][2][lane]);
        u64 aif1 = add2(am1, px[1][ow][0][lane]);
        u64 ago1 = add2(gm1, px[1][ow][1][lane]);
        u64 ya1  = add2(ym1, px[1][ow][2][lane]);

        if (t > 0) {   // ya used h_t = hs[t-1] -> y[t-1]
            float a, b;
            upk2(ya0, a, b);
            yA[(size_t)(t - 1) * 64 + lane] = a;
            yA[(size_t)(t - 1) * 64 + 32 + lane] = b;
            upk2(ya1, a, b);
            yB[(size_t)(t - 1) * 64 + lane] = a;
            yB[(size_t)(t - 1) * 64 + 32 + lane] = b;
        }

        float zi, zf, zg, zo;
        upk2(aif0, zi, zf); upk2(ago0, zg, zo);
        h0 = cellf(zi, zf, zg, zo, cc0);
        upk2(aif1, zi, zf); upk2(ago1, zg, zo);
        h1 = cellf(zi, zf, zg, zo, cc1);

        const int nb = cb ^ 1;
        hds[nb][wid][lane] = pk2(h0, h0);
        hds[nb][2 + wid][lane] = pk2(h1, h1);
        __syncthreads();
    }

    // epilogue: y[127] from h_128 (hds buf 0 after t=127; synced in-loop)
    {
        u64 ya0 = bo, ya1 = bo;
#pragma unroll
        for (int kk = 0; kk < 32; kk += 2) {
            ulonglong2 hA = *(const ulonglong2*)&hds[0][wid][kk];
            ulonglong2 hB = *(const ulonglong2*)&hds[0][2 + wid][kk];
            u64 wo0 = Wos[kk * 32 + lane];
            u64 wo1 = Wos[(kk + 1) * 32 + lane];
            ya0 = fma2(hA.x, wo0, ya0);
            ya0 = fma2(hA.y, wo1, ya0);
            ya1 = fma2(hB.x, wo0, ya1);
            ya1 = fma2(hB.y, wo1, ya1);
        }
        float a, b;
        upk2(ya0, a, b);
        yA[(size_t)127 * 64 + lane] = a;
        yA[(size_t)127 * 64 + 32 + lane] = b;
        upk2(ya1, a, b);
        yB[(size_t)127 * 64 + lane] = a;
        yB[(size_t)127 * 64 + 32 + lane] = b;
    }
}

// =====================================================================
extern "C" void kernel_launch(void* const* d_in, const int* in_sizes, int n_in,
                              void* d_out, int out_size)
{
    const float* x    = (const float*)d_in[0];
    const float* We   = (const float*)d_in[1];
    const float* Ue   = (const float*)d_in[2];
    const float* be   = (const float*)d_in[3];
    const float* Wd   = (const float*)d_in[4];
    const float* Ud   = (const float*)d_in[5];
    const float* bd   = (const float*)d_in[6];
    const float* Wout = (const float*)d_in[7];
    const float* bout = (const float*)d_in[8];
    float* y = (float*)d_out;

    cudaFuncSetAttribute(k_xz, cudaFuncAttributeMaxDynamicSharedMemorySize, SMX_TOTAL);

    k_prep<<<1, 256>>>(We, be);
    k_xz<<<8192, 128, SMX_TOTAL>>>(x);
    k_rnn<<<1024, 64>>>(Ue, Ud, Wd, bd, Wout, bout, y);
}